// round 15
// baseline (speedup 1.0000x reference)
#include <cuda_runtime.h>
#include <cuda_fp16.h>
#include <cstdint>

// ---------------- problem constants ----------------
#define NODES 50000
#define RELS  3
#define EDGES 600000
#define D_IN  128
#define D_HID 256
#define D_OUT 128

#define SCAN_N (RELS * NODES)          // 150000 segments
#define SCAN_B 512
#define SCAN_BLOCKS ((SCAN_N + SCAN_B - 1) / SCAN_B)   // 293

// ---------------- scratch ----------------
__device__ __half g_xh  [(size_t)NODES * D_IN];           // 12.8 MB
__device__ __half g_seg1[(size_t)RELS * NODES * D_IN];    // 38.4 MB
__device__ __half g_h   [(size_t)NODES * D_HID];          // 25.6 MB
__device__ __half g_Yh  [(size_t)NODES * 3 * D_OUT];      // 38.4 MB, row layout [node][3*128]
__device__ float  g_Ys  [(size_t)NODES * D_OUT];          // 25.6 MB (bias pre-added)
__device__ int    g_cnt [SCAN_N];
__device__ int    g_offs[SCAN_N + 1];                     // partial (within-block) prefixes
__device__ int    g_bsum[SCAN_B];                         // block sums -> exclusive-scanned in place
__device__ int    g_scan_done;
__device__ int    g_elist[(size_t)RELS * EDGES];          // 7.2 MB
__device__ __half g_W1h [D_HID * (4 * D_IN)];             // [256][512] fp16, transposed
__device__ __half g_W2h [(4 * D_OUT) * D_HID];            // [512][256] fp16, transposed
__device__ float  g_b1s [D_HID];
__device__ float  g_b2s [D_OUT];

// ---------------- tiny zero for cnt + scan_done (precedes fused cnt+prep) ----------------
__global__ void zero_cnt_kernel(int4* __restrict__ p, int* __restrict__ scan_done) {
    int i = blockIdx.x * blockDim.x + threadIdx.x;
    if (i < SCAN_N / 4) p[i] = make_int4(0, 0, 0, 0);
    if (i == 0) *scan_done = 0;
}

// ---------------- fused cnt + prep: count degrees AND convert W1/W2/x, one launch ----------
__global__ void cnt_prep_kernel(const int* __restrict__ dst, int* __restrict__ cnt,
                                const float4* __restrict__ x,
                                const float* __restrict__ Wself1, const float* __restrict__ Wneigh1,
                                const float* __restrict__ b1,
                                const float* __restrict__ Wself2, const float* __restrict__ Wneigh2,
                                const float* __restrict__ b2,
                                __half* __restrict__ W1t, __half* __restrict__ W2t,
                                uint4* __restrict__ xh,
                                float* __restrict__ b1s, float* __restrict__ b2s) {
    const int t = blockIdx.x * blockDim.x + threadIdx.x;

    if (t < RELS * EDGES) {
        int r = t / EDGES;
        atomicAdd(&cnt[r * NODES + dst[t]], 1);
    }

    if (t < NODES * D_IN / 8) {
        float4 a = x[(long)t * 2], b = x[(long)t * 2 + 1];
        __half2 h0 = __floats2half2_rn(a.x, a.y);
        __half2 h1 = __floats2half2_rn(a.z, a.w);
        __half2 h2 = __floats2half2_rn(b.x, b.y);
        __half2 h3 = __floats2half2_rn(b.z, b.w);
        uint4 o;
        o.x = *reinterpret_cast<unsigned*>(&h0);
        o.y = *reinterpret_cast<unsigned*>(&h1);
        o.z = *reinterpret_cast<unsigned*>(&h2);
        o.w = *reinterpret_cast<unsigned*>(&h3);
        xh[t] = o;
    }

    if (t < D_HID * 4 * D_IN) {
        int j = t / (4 * D_IN);
        int k = t - j * (4 * D_IN);
        float v;
        if (k < D_IN) {
            v = Wself1[(size_t)k * D_HID + j]
              + Wself1[((size_t)D_IN + k) * D_HID + j]
              + Wself1[((size_t)2 * D_IN + k) * D_HID + j];
        } else {
            int r = (k - D_IN) / D_IN;
            int d = (k - D_IN) - r * D_IN;
            v = Wneigh1[((size_t)r * D_IN + d) * D_HID + j];
        }
        W1t[t] = __float2half_rn(v);
    }

    if (t < (4 * D_OUT) * D_HID) {
        int c = t / D_HID;
        int k = t - c * D_HID;
        float v;
        if (c < 3 * D_OUT) {
            int r = c / D_OUT;
            int j = c - r * D_OUT;
            v = Wneigh2[((size_t)r * D_HID + k) * D_OUT + j];
        } else {
            int j = c - 3 * D_OUT;
            v = Wself2[(size_t)k * D_OUT + j]
              + Wself2[((size_t)D_HID + k) * D_OUT + j]
              + Wself2[((size_t)2 * D_HID + k) * D_OUT + j];
        }
        W2t[t] = __float2half_rn(v);
    }

    if (t < D_HID) b1s[t] = b1[t] + b1[D_HID + t] + b1[2 * D_HID + t];
    if (t < D_OUT) b2s[t] = b2[t] + b2[D_OUT + t] + b2[2 * D_OUT + t];
}

// ---------------- fused scan: per-block prefix + last-block scans bsum in place ----------
// offs[i] (i <= SCAN_N) = within-block exclusive prefix; bsum becomes exclusive block scan.
// final offset(w) = offs[w] + bsum[w >> 9]   (consumers compute this inline)
__global__ void scan_fused_kernel(const int* __restrict__ cnt, int* __restrict__ offs,
                                  int* __restrict__ bsum, int* __restrict__ scan_done) {
    __shared__ int wsum[16];
    int i = blockIdx.x * SCAN_B + threadIdx.x;
    int lane = threadIdx.x & 31, wid = threadIdx.x >> 5;
    int v = (i < SCAN_N) ? cnt[i] : 0;
    int s = v;
#pragma unroll
    for (int o = 1; o < 32; o <<= 1) {
        int t = __shfl_up_sync(0xffffffffu, s, o);
        if (lane >= o) s += t;
    }
    if (lane == 31) wsum[wid] = s;
    __syncthreads();
    if (wid == 0) {
        int ws = (lane < 16) ? wsum[lane] : 0;
#pragma unroll
        for (int o = 1; o < 16; o <<= 1) {
            int t = __shfl_up_sync(0xffffffffu, ws, o);
            if (lane >= o) ws += t;
        }
        if (lane < 16) wsum[lane] = ws;
    }
    __syncthreads();
    int incl = s + ((wid > 0) ? wsum[wid - 1] : 0);
    if (i <= SCAN_N) offs[i] = incl - v;     // includes the SCAN_N boundary entry
    if (threadIdx.x == SCAN_B - 1) bsum[blockIdx.x] = incl;

    // last block to finish scans bsum in place (exclusive)
    __shared__ int is_last;
    __threadfence();
    __syncthreads();
    if (threadIdx.x == 0) {
        int prev = atomicAdd(scan_done, 1);
        is_last = (prev == gridDim.x - 1);
    }
    __syncthreads();
    if (!is_last) return;

    int bv = (threadIdx.x < SCAN_BLOCKS) ? bsum[threadIdx.x] : 0;
    int bs = bv;
#pragma unroll
    for (int o = 1; o < 32; o <<= 1) {
        int t = __shfl_up_sync(0xffffffffu, bs, o);
        if (lane >= o) bs += t;
    }
    if (lane == 31) wsum[wid] = bs;
    __syncthreads();
    if (wid == 0) {
        int ws = (lane < 16) ? wsum[lane] : 0;
#pragma unroll
        for (int o = 1; o < 16; o <<= 1) {
            int t = __shfl_up_sync(0xffffffffu, ws, o);
            if (lane >= o) ws += t;
        }
        if (lane < 16) wsum[lane] = ws;
    }
    __syncthreads();
    int bincl = bs + ((wid > 0) ? wsum[wid - 1] : 0);
    if (threadIdx.x < SCAN_BLOCKS) bsum[threadIdx.x] = bincl - bv;
}

// uses cnt as cursor (atomicSub); cnt dead afterwards
__global__ void fill_kernel(const int* __restrict__ src, const int* __restrict__ dst,
                            const int* __restrict__ offs, const int* __restrict__ bscan,
                            int* __restrict__ cnt, int* __restrict__ elist) {
    int e = blockIdx.x * blockDim.x + threadIdx.x;
    if (e >= RELS * EDGES) return;
    int r = e / EDGES;
    int idx = r * NODES + dst[e];
    int base = offs[idx] + __ldg(bscan + (idx >> 9));
    int pos = base + (atomicSub(&cnt[idx], 1) - 1);
    elist[pos] = src[e];
}

// ---------------- gather-accumulate helper: batches of 8 / 4 / 1 ----------------
__device__ __forceinline__ void gather_seg(const __half* __restrict__ base, size_t rowStride,
                                           const int* __restrict__ elist, int beg, int end,
                                           int lane, float4& s) {
    for (int i = beg; i < end; i += 32) {
        int nid = (i + lane < end) ? elist[i + lane] : 0;
        int cnt = min(32, end - i);
        int j = 0;
        for (; j + 8 <= cnt; j += 8) {
            int sid[8];
#pragma unroll
            for (int q = 0; q < 8; q++) sid[q] = __shfl_sync(0xffffffffu, nid, j + q);
            uint2 v[8];
#pragma unroll
            for (int q = 0; q < 8; q++)
                v[q] = __ldg(((const uint2*)(base + (size_t)sid[q] * rowStride)) + lane);
#pragma unroll
            for (int q = 0; q < 8; q++) {
                float2 f0 = __half22float2(*reinterpret_cast<__half2*>(&v[q].x));
                float2 f1 = __half22float2(*reinterpret_cast<__half2*>(&v[q].y));
                s.x += f0.x; s.y += f0.y; s.z += f1.x; s.w += f1.y;
            }
        }
        for (; j + 4 <= cnt; j += 4) {
            int sid[4];
#pragma unroll
            for (int q = 0; q < 4; q++) sid[q] = __shfl_sync(0xffffffffu, nid, j + q);
            uint2 v[4];
#pragma unroll
            for (int q = 0; q < 4; q++)
                v[q] = __ldg(((const uint2*)(base + (size_t)sid[q] * rowStride)) + lane);
#pragma unroll
            for (int q = 0; q < 4; q++) {
                float2 f0 = __half22float2(*reinterpret_cast<__half2*>(&v[q].x));
                float2 f1 = __half22float2(*reinterpret_cast<__half2*>(&v[q].y));
                s.x += f0.x; s.y += f0.y; s.z += f1.x; s.w += f1.y;
            }
        }
        for (; j < cnt; j++) {
            int sid = __shfl_sync(0xffffffffu, nid, j);
            uint2 v = __ldg(((const uint2*)(base + (size_t)sid * rowStride)) + lane);
            float2 f0 = __half22float2(*reinterpret_cast<__half2*>(&v.x));
            float2 f1 = __half22float2(*reinterpret_cast<__half2*>(&v.y));
            s.x += f0.x; s.y += f0.y; s.z += f1.x; s.w += f1.y;
        }
    }
}

// final offset helper
__device__ __forceinline__ int foffs(const int* __restrict__ offs,
                                     const int* __restrict__ bscan, int w) {
    return __ldg(offs + w) + __ldg(bscan + (w >> 9));
}

// ---------------- reduce 1: seg1[w] = fp16(mean of fp16 x[src]) ----------------
__global__ void reduce1_kernel(const __half* __restrict__ xh, const int* __restrict__ offs,
                               const int* __restrict__ bscan, const int* __restrict__ elist,
                               __half* __restrict__ seg) {
    int w = (blockIdx.x * blockDim.x + threadIdx.x) >> 5;
    int lane = threadIdx.x & 31;
    if (w >= SCAN_N) return;
    int beg = foffs(offs, bscan, w), end = foffs(offs, bscan, w + 1);
    float4 s = make_float4(0.f, 0.f, 0.f, 0.f);
    gather_seg(xh, D_IN, elist, beg, end, lane, s);
    float sc = 1.f / fmaxf((float)(end - beg), 1.f);
    uint2 o;
    __half2 h0 = __floats2half2_rn(s.x * sc, s.y * sc);
    __half2 h1 = __floats2half2_rn(s.z * sc, s.w * sc);
    o.x = *reinterpret_cast<unsigned*>(&h0);
    o.y = *reinterpret_cast<unsigned*>(&h1);
    ((uint2*)(seg + (size_t)w * D_IN))[lane] = o;
}

// ---------------- fused reduce 2 + final (one warp per node, row-layout Yh) ----------------
__global__ void reduce2_final_kernel(const __half* __restrict__ Yh, const float* __restrict__ Ys,
                                     const int* __restrict__ offs, const int* __restrict__ bscan,
                                     const int* __restrict__ elist, float* __restrict__ out) {
    int d = (blockIdx.x * blockDim.x + threadIdx.x) >> 5;
    int lane = threadIdx.x & 31;
    if (d >= NODES) return;

    int beg0 = foffs(offs, bscan, d),             end0 = foffs(offs, bscan, d + 1);
    int beg1 = foffs(offs, bscan, NODES + d),     end1 = foffs(offs, bscan, NODES + d + 1);
    int beg2 = foffs(offs, bscan, 2 * NODES + d), end2 = foffs(offs, bscan, 2 * NODES + d + 1);
    float4 acc = __ldg(((const float4*)(Ys + (size_t)d * D_OUT)) + lane);

    int begs[3] = {beg0, beg1, beg2};
    int ends[3] = {end0, end1, end2};
#pragma unroll
    for (int r = 0; r < RELS; r++) {
        int beg = begs[r], end = ends[r];
        if (beg == end) continue;
        float4 s = make_float4(0.f, 0.f, 0.f, 0.f);
        gather_seg(Yh + r * D_OUT, 3 * D_OUT, elist, beg, end, lane, s);
        float sc = 1.f / (float)(end - beg);
        acc.x += s.x * sc; acc.y += s.y * sc; acc.z += s.z * sc; acc.w += s.w * sc;
    }
    ((float4*)(out + (size_t)d * D_OUT))[lane] = acc;
}

// ---------------- fp16 HMMA GEMM: cp.async 3-stage, BK=64, ldmatrix fragments ----------------
// biasMode: 0=none, 1=bias[col] on all cols, 2=bias[col-halfCols] on fp32 cols only
#define BK 64
#define TSTRIDE 72
#define TILE_H (128 * TSTRIDE)
#define NSTAGE 3
#define GEMM_SMEM (NSTAGE * 2 * TILE_H * 2)   // 110592 bytes

__device__ __forceinline__ void ldsm_x4(uint32_t addr, unsigned& r0, unsigned& r1,
                                        unsigned& r2, unsigned& r3) {
    asm volatile("ldmatrix.sync.aligned.m8n8.x4.shared.b16 {%0,%1,%2,%3}, [%4];"
                 : "=r"(r0), "=r"(r1), "=r"(r2), "=r"(r3) : "r"(addr));
}

template <int D>
__global__ __launch_bounds__(256, 2)
void gemm_f16_kernel(const __half* __restrict__ feat, const __half* __restrict__ seg,
                     const __half* __restrict__ Bw, const float* __restrict__ bias,
                     float* __restrict__ Cf, __half* __restrict__ Ch,
                     int M, int N, int K, int halfCols, int doRelu, int biasMode) {
    extern __shared__ __half smp[];
    __half* As = smp;
    __half* Bs = smp + NSTAGE * TILE_H;
    const uint32_t As_u = (uint32_t)__cvta_generic_to_shared(As);
    const uint32_t Bs_u = (uint32_t)__cvta_generic_to_shared(Bs);

    const int tid  = threadIdx.x;
    const int lane = tid & 31;
    const int warp = tid >> 5;
    const int warpM = (warp >> 2) * 64;
    const int warpN = (warp & 3) * 32;
    const int block_row = blockIdx.x * 128;
    const int block_col = blockIdx.y * 128;

    const int ld_r0 = tid >> 1;
    const int ld_c0 = (tid & 1) * 32;

    const int a_row_lane = ((lane >> 3) & 1) * 8 + (lane & 7);
    const int a_k_lane   = (lane >> 4) * 8;
    const int b_n_lane = (lane >> 4) * 8 + (lane & 7);
    const int b_k_lane = ((lane >> 3) & 1) * 8;

    float acc[4][4][4];
#pragma unroll
    for (int i = 0; i < 4; i++)
#pragma unroll
        for (int j = 0; j < 4; j++)
#pragma unroll
            for (int c = 0; c < 4; c++) acc[i][j][c] = 0.f;

    auto load_stage = [&](int buf, int kb) {
        const int chunk = kb / D;
        const int col0 = kb - chunk * D;
        const __half* abase = (chunk == 0) ? feat : (seg + (size_t)(chunk - 1) * NODES * D);
        int gr = block_row + ld_r0;
        const __half* ag = abase + (size_t)gr * D + col0 + ld_c0;
        uint32_t sa = As_u + (uint32_t)(buf * TILE_H + ld_r0 * TSTRIDE + ld_c0) * 2u;
        int sz = (gr < M) ? 16 : 0;
#pragma unroll
        for (int l = 0; l < 4; l++) {
            asm volatile("cp.async.cg.shared.global [%0], [%1], 16, %2;"
                         :: "r"(sa + l * 16u), "l"(ag + l * 8), "r"(sz));
        }
        const __half* bg = Bw + (size_t)(block_col + ld_r0) * K + kb + ld_c0;
        uint32_t sb = Bs_u + (uint32_t)(buf * TILE_H + ld_r0 * TSTRIDE + ld_c0) * 2u;
#pragma unroll
        for (int l = 0; l < 4; l++) {
            asm volatile("cp.async.cg.shared.global [%0], [%1], 16;"
                         :: "r"(sb + l * 16u), "l"(bg + l * 8));
        }
        asm volatile("cp.async.commit_group;");
    };

    const int T = K / BK;
    load_stage(0, 0);
    load_stage(1, BK);

    for (int t = 0; t < T; t++) {
        if (t + 1 < T) {
            asm volatile("cp.async.wait_group 1;");
        } else {
            asm volatile("cp.async.wait_group 0;");
        }
        __syncthreads();
        if (t + 2 < T) load_stage((t + 2) % NSTAGE, (t + 2) * BK);

        int buf = t % NSTAGE;
        const uint32_t At_u = As_u + (uint32_t)(buf * TILE_H) * 2u;
        const uint32_t Bt_u = Bs_u + (uint32_t)(buf * TILE_H) * 2u;
#pragma unroll
        for (int k16 = 0; k16 < BK / 16; k16++) {
            const int kbase = k16 * 16;
            unsigned a[4][4];
#pragma unroll
            for (int mt = 0; mt < 4; mt++) {
                uint32_t addr = At_u + (uint32_t)((warpM + mt * 16 + a_row_lane) * TSTRIDE
                                                  + kbase + a_k_lane) * 2u;
                ldsm_x4(addr, a[mt][0], a[mt][1], a[mt][2], a[mt][3]);
            }
            unsigned b[4][2];
#pragma unroll
            for (int ntp = 0; ntp < 4; ntp += 2) {
                uint32_t addr = Bt_u + (uint32_t)((warpN + ntp * 8 + b_n_lane) * TSTRIDE
                                                  + kbase + b_k_lane) * 2u;
                ldsm_x4(addr, b[ntp][0], b[ntp][1], b[ntp + 1][0], b[ntp + 1][1]);
            }
#pragma unroll
            for (int mt = 0; mt < 4; mt++)
#pragma unroll
                for (int nt = 0; nt < 4; nt++) {
                    asm volatile(
                        "mma.sync.aligned.m16n8k16.row.col.f32.f16.f16.f32 "
                        "{%0,%1,%2,%3}, {%4,%5,%6,%7}, {%8,%9}, {%0,%1,%2,%3};"
                        : "+f"(acc[mt][nt][0]), "+f"(acc[mt][nt][1]),
                          "+f"(acc[mt][nt][2]), "+f"(acc[mt][nt][3])
                        : "r"(a[mt][0]), "r"(a[mt][1]), "r"(a[mt][2]), "r"(a[mt][3]),
                          "r"(b[nt][0]), "r"(b[nt][1]));
                }
        }
        __syncthreads();
    }

    const int fStride = N - halfCols;
#pragma unroll
    for (int mt = 0; mt < 4; mt++) {
#pragma unroll
        for (int nt = 0; nt < 4; nt++) {
            int col = block_col + warpN + nt * 8 + (lane & 3) * 2;
            float bx = 0.f, by = 0.f;
            if (biasMode == 1) { bx = bias[col]; by = bias[col + 1]; }
            else if (biasMode == 2 && col >= halfCols) {
                bx = bias[col - halfCols]; by = bias[col - halfCols + 1];
            }
#pragma unroll
            for (int half = 0; half < 2; half++) {
                int row = block_row + warpM + mt * 16 + (lane >> 2) + half * 8;
                if (row >= M) continue;
                float vx = acc[mt][nt][half * 2 + 0] + bx;
                float vy = acc[mt][nt][half * 2 + 1] + by;
                if (doRelu) { vx = fmaxf(vx, 0.f); vy = fmaxf(vy, 0.f); }
                if (col < halfCols) {
                    *(__half2*)(Ch + (size_t)row * halfCols + col) = __floats2half2_rn(vx, vy);
                } else {
                    *(float2*)(Cf + (size_t)row * fStride + (col - halfCols)) = make_float2(vx, vy);
                }
            }
        }
    }
}

// ---------------- launch ----------------
extern "C" void kernel_launch(void* const* d_in, const int* in_sizes, int n_in,
                              void* d_out, int out_size) {
    const float* x      = (const float*)d_in[0];
    const int*   src    = (const int*)  d_in[1];
    const int*   dst    = (const int*)  d_in[2];
    const float* Wself1 = (const float*)d_in[3];
    const float* Wneigh1= (const float*)d_in[4];
    const float* b1     = (const float*)d_in[5];
    const float* Wself2 = (const float*)d_in[6];
    const float* Wneigh2= (const float*)d_in[7];
    const float* b2     = (const float*)d_in[8];
    float* out = (float*)d_out;

    float *Ys, *b1s, *b2s;
    __half *xh, *seg1, *h, *Yh, *W1h, *W2h;
    int *cnt, *offs, *bsum, *elist, *scan_done;
    cudaGetSymbolAddress((void**)&xh,   g_xh);
    cudaGetSymbolAddress((void**)&seg1, g_seg1);
    cudaGetSymbolAddress((void**)&h,    g_h);
    cudaGetSymbolAddress((void**)&Yh,   g_Yh);
    cudaGetSymbolAddress((void**)&Ys,   g_Ys);
    cudaGetSymbolAddress((void**)&cnt,  g_cnt);
    cudaGetSymbolAddress((void**)&offs, g_offs);
    cudaGetSymbolAddress((void**)&bsum, g_bsum);
    cudaGetSymbolAddress((void**)&elist,g_elist);
    cudaGetSymbolAddress((void**)&scan_done, g_scan_done);
    cudaGetSymbolAddress((void**)&W1h,  g_W1h);
    cudaGetSymbolAddress((void**)&W2h,  g_W2h);
    cudaGetSymbolAddress((void**)&b1s,  g_b1s);
    cudaGetSymbolAddress((void**)&b2s,  g_b2s);

    cudaFuncSetAttribute(gemm_f16_kernel<D_IN>,
                         cudaFuncAttributeMaxDynamicSharedMemorySize, GEMM_SMEM);
    cudaFuncSetAttribute(gemm_f16_kernel<D_HID>,
                         cudaFuncAttributeMaxDynamicSharedMemorySize, GEMM_SMEM);

    // ---- zero cnt + scan_done, then fused cnt + all prep ----
    zero_cnt_kernel<<<(SCAN_N / 4 + 255) / 256, 256>>>((int4*)cnt, scan_done);
    cnt_prep_kernel<<<(RELS * EDGES + 255) / 256, 256>>>(
        dst, cnt, (const float4*)x,
        Wself1, Wneigh1, b1, Wself2, Wneigh2, b2,
        W1h, W2h, (uint4*)xh, b1s, b2s);

    // ---- fused scan (block prefixes + last-block bsum scan), then fill ----
    scan_fused_kernel<<<SCAN_BLOCKS, SCAN_B>>>(cnt, offs, bsum, scan_done);
    fill_kernel<<<(RELS * EDGES + 255) / 256, 256>>>(src, dst, offs, bsum, cnt, elist);

    const int reduce_blocks = (SCAN_N * 32 + 255) / 256;
    const int mblocks = (NODES + 127) / 128;

    // ---- layer 1: fp16 means -> seg1, fp16 GEMM -> h (relu+bias, fp16 out) ----
    reduce1_kernel<<<reduce_blocks, 256>>>(xh, offs, bsum, elist, seg1);
    {
        dim3 grid(mblocks, D_HID / 128);
        gemm_f16_kernel<D_IN><<<grid, 256, GEMM_SMEM>>>(xh, seg1, W1h, b1s, nullptr, h,
                                                        NODES, D_HID, 4 * D_IN,
                                                        D_HID, 1, 1);
    }

    // ---- layer 2: fp16 GEMM -> [Yh fp16 | Ys fp32+bias], fused reduce+final -> out ----
    {
        dim3 grid(mblocks, (4 * D_OUT) / 128);
        gemm_f16_kernel<D_HID><<<grid, 256, GEMM_SMEM>>>(h, nullptr, W2h, b2s, Ys, Yh,
                                                         NODES, 4 * D_OUT, D_HID,
                                                         3 * D_OUT, 0, 2);
    }
    reduce2_final_kernel<<<(NODES * 32 + 255) / 256, 256>>>(Yh, Ys, offs, bsum, elist, out);
}

// round 16
// speedup vs baseline: 1.0213x; 1.0213x over previous
#include <cuda_runtime.h>
#include <cuda_fp16.h>
#include <cstdint>

// ---------------- problem constants ----------------
#define NODES 50000
#define RELS  3
#define EDGES 600000
#define D_IN  128
#define D_HID 256
#define D_OUT 128

#define SCAN_N (RELS * NODES)          // 150000 segments
#define SCAN_B 512
#define SCAN_BLOCKS ((SCAN_N + SCAN_B - 1) / SCAN_B)   // 293

// ---------------- scratch ----------------
__device__ __half g_xh  [(size_t)NODES * D_IN];           // 12.8 MB
__device__ __half g_seg1[(size_t)RELS * NODES * D_IN];    // 38.4 MB
__device__ __half g_h   [(size_t)NODES * D_HID];          // 25.6 MB
__device__ __half g_Yh  [(size_t)NODES * 3 * D_OUT];      // 38.4 MB, row layout [node][3*128]
__device__ float  g_Ys  [(size_t)NODES * D_OUT];          // 25.6 MB (bias pre-added)
__device__ int    g_cnt [SCAN_N];
__device__ int    g_offs[SCAN_N + 1];
__device__ int    g_bsum[SCAN_B];
__device__ int    g_epos[(size_t)RELS * EDGES];           // 7.2 MB per-edge rank in segment
__device__ int    g_elist[(size_t)RELS * EDGES];          // 7.2 MB
__device__ __half g_W1h [D_HID * (4 * D_IN)];             // [256][512] fp16, transposed
__device__ __half g_W2h [(4 * D_OUT) * D_HID];            // [512][256] fp16, transposed
__device__ float  g_b1s [D_HID];
__device__ float  g_b2s [D_OUT];

// ---------------- tiny zero for cnt (must precede fused cnt+prep) ----------------
__global__ void zero_cnt_kernel(int4* __restrict__ p) {
    int i = blockIdx.x * blockDim.x + threadIdx.x;
    if (i < SCAN_N / 4) p[i] = make_int4(0, 0, 0, 0);
}

// ---------------- fused cnt + prep: count degrees (capturing per-edge rank) + convert ----
__global__ void cnt_prep_kernel(const int* __restrict__ dst, int* __restrict__ cnt,
                                int* __restrict__ epos,
                                const float4* __restrict__ x,
                                const float* __restrict__ Wself1, const float* __restrict__ Wneigh1,
                                const float* __restrict__ b1,
                                const float* __restrict__ Wself2, const float* __restrict__ Wneigh2,
                                const float* __restrict__ b2,
                                __half* __restrict__ W1t, __half* __restrict__ W2t,
                                uint4* __restrict__ xh,
                                float* __restrict__ b1s, float* __restrict__ b2s) {
    const int t = blockIdx.x * blockDim.x + threadIdx.x;

    if (t < RELS * EDGES) {
        int r = t / EDGES;
        epos[t] = atomicAdd(&cnt[r * NODES + dst[t]], 1);
    }

    // x -> fp16 (NODES*D_IN/8 = 800000 uint4 stores)
    if (t < NODES * D_IN / 8) {
        float4 a = x[(long)t * 2], b = x[(long)t * 2 + 1];
        __half2 h0 = __floats2half2_rn(a.x, a.y);
        __half2 h1 = __floats2half2_rn(a.z, a.w);
        __half2 h2 = __floats2half2_rn(b.x, b.y);
        __half2 h3 = __floats2half2_rn(b.z, b.w);
        uint4 o;
        o.x = *reinterpret_cast<unsigned*>(&h0);
        o.y = *reinterpret_cast<unsigned*>(&h1);
        o.z = *reinterpret_cast<unsigned*>(&h2);
        o.w = *reinterpret_cast<unsigned*>(&h3);
        xh[t] = o;
    }

    // W1h [256][512]
    if (t < D_HID * 4 * D_IN) {
        int j = t / (4 * D_IN);
        int k = t - j * (4 * D_IN);
        float v;
        if (k < D_IN) {
            v = Wself1[(size_t)k * D_HID + j]
              + Wself1[((size_t)D_IN + k) * D_HID + j]
              + Wself1[((size_t)2 * D_IN + k) * D_HID + j];
        } else {
            int r = (k - D_IN) / D_IN;
            int d = (k - D_IN) - r * D_IN;
            v = Wneigh1[((size_t)r * D_IN + d) * D_HID + j];
        }
        W1t[t] = __float2half_rn(v);
    }

    // W2h [512][256]
    if (t < (4 * D_OUT) * D_HID) {
        int c = t / D_HID;
        int k = t - c * D_HID;
        float v;
        if (c < 3 * D_OUT) {
            int r = c / D_OUT;
            int j = c - r * D_OUT;
            v = Wneigh2[((size_t)r * D_HID + k) * D_OUT + j];
        } else {
            int j = c - 3 * D_OUT;
            v = Wself2[(size_t)k * D_OUT + j]
              + Wself2[((size_t)D_HID + k) * D_OUT + j]
              + Wself2[((size_t)2 * D_HID + k) * D_OUT + j];
        }
        W2t[t] = __float2half_rn(v);
    }

    if (t < D_HID) b1s[t] = b1[t] + b1[D_HID + t] + b1[2 * D_HID + t];
    if (t < D_OUT) b2s[t] = b2[t] + b2[D_OUT + t] + b2[2 * D_OUT + t];
}

// ---------------- CSR scans ----------------
__global__ void scan1_kernel(const int* __restrict__ cnt, int* __restrict__ offs,
                             int* __restrict__ bsum) {
    __shared__ int wsum[16];
    int i = blockIdx.x * SCAN_B + threadIdx.x;
    int lane = threadIdx.x & 31, wid = threadIdx.x >> 5;
    int v = (i < SCAN_N) ? cnt[i] : 0;
    int s = v;
#pragma unroll
    for (int o = 1; o < 32; o <<= 1) {
        int t = __shfl_up_sync(0xffffffffu, s, o);
        if (lane >= o) s += t;
    }
    if (lane == 31) wsum[wid] = s;
    __syncthreads();
    if (wid == 0) {
        int ws = (lane < 16) ? wsum[lane] : 0;
#pragma unroll
        for (int o = 1; o < 16; o <<= 1) {
            int t = __shfl_up_sync(0xffffffffu, ws, o);
            if (lane >= o) ws += t;
        }
        if (lane < 16) wsum[lane] = ws;
    }
    __syncthreads();
    int incl = s + ((wid > 0) ? wsum[wid - 1] : 0);
    if (i < SCAN_N) offs[i] = incl - v;
    if (threadIdx.x == SCAN_B - 1) bsum[blockIdx.x] = incl;
}

__global__ void scan2_kernel(int* __restrict__ bsum, int nb) {
    __shared__ int wsum[16];
    int lane = threadIdx.x & 31, wid = threadIdx.x >> 5;
    int v = (threadIdx.x < nb) ? bsum[threadIdx.x] : 0;
    int s = v;
#pragma unroll
    for (int o = 1; o < 32; o <<= 1) {
        int t = __shfl_up_sync(0xffffffffu, s, o);
        if (lane >= o) s += t;
    }
    if (lane == 31) wsum[wid] = s;
    __syncthreads();
    if (wid == 0) {
        int ws = (lane < 16) ? wsum[lane] : 0;
#pragma unroll
        for (int o = 1; o < 16; o <<= 1) {
            int t = __shfl_up_sync(0xffffffffu, ws, o);
            if (lane >= o) ws += t;
        }
        if (lane < 16) wsum[lane] = ws;
    }
    __syncthreads();
    int incl = s + ((wid > 0) ? wsum[wid - 1] : 0);
    if (threadIdx.x < nb) bsum[threadIdx.x] = incl - v;
}

__global__ void scan3_kernel(int* __restrict__ offs, const int* __restrict__ bsum) {
    int i = blockIdx.x * SCAN_B + threadIdx.x;
    if (i < SCAN_N) offs[i] += bsum[blockIdx.x];
    if (i == 0) offs[SCAN_N] = RELS * EDGES;
}

// ---------------- fill: atomic-free scatter using precomputed per-edge rank ----------------
__global__ void fill_kernel(const int* __restrict__ src, const int* __restrict__ dst,
                            const int* __restrict__ offs, const int* __restrict__ epos,
                            int* __restrict__ elist) {
    int e = blockIdx.x * blockDim.x + threadIdx.x;
    if (e >= RELS * EDGES) return;
    int r = e / EDGES;
    int idx = r * NODES + dst[e];
    elist[__ldg(offs + idx) + epos[e]] = src[e];
}

// ---------------- gather-accumulate helper: batches of 8 / 4 / 1 ----------------
__device__ __forceinline__ void gather_seg(const __half* __restrict__ base, size_t rowStride,
                                           const int* __restrict__ elist, int beg, int end,
                                           int lane, float4& s) {
    for (int i = beg; i < end; i += 32) {
        int nid = (i + lane < end) ? elist[i + lane] : 0;
        int cnt = min(32, end - i);
        int j = 0;
        for (; j + 8 <= cnt; j += 8) {
            int sid[8];
#pragma unroll
            for (int q = 0; q < 8; q++) sid[q] = __shfl_sync(0xffffffffu, nid, j + q);
            uint2 v[8];
#pragma unroll
            for (int q = 0; q < 8; q++)
                v[q] = __ldg(((const uint2*)(base + (size_t)sid[q] * rowStride)) + lane);
#pragma unroll
            for (int q = 0; q < 8; q++) {
                float2 f0 = __half22float2(*reinterpret_cast<__half2*>(&v[q].x));
                float2 f1 = __half22float2(*reinterpret_cast<__half2*>(&v[q].y));
                s.x += f0.x; s.y += f0.y; s.z += f1.x; s.w += f1.y;
            }
        }
        for (; j + 4 <= cnt; j += 4) {
            int sid[4];
#pragma unroll
            for (int q = 0; q < 4; q++) sid[q] = __shfl_sync(0xffffffffu, nid, j + q);
            uint2 v[4];
#pragma unroll
            for (int q = 0; q < 4; q++)
                v[q] = __ldg(((const uint2*)(base + (size_t)sid[q] * rowStride)) + lane);
#pragma unroll
            for (int q = 0; q < 4; q++) {
                float2 f0 = __half22float2(*reinterpret_cast<__half2*>(&v[q].x));
                float2 f1 = __half22float2(*reinterpret_cast<__half2*>(&v[q].y));
                s.x += f0.x; s.y += f0.y; s.z += f1.x; s.w += f1.y;
            }
        }
        for (; j < cnt; j++) {
            int sid = __shfl_sync(0xffffffffu, nid, j);
            uint2 v = __ldg(((const uint2*)(base + (size_t)sid * rowStride)) + lane);
            float2 f0 = __half22float2(*reinterpret_cast<__half2*>(&v.x));
            float2 f1 = __half22float2(*reinterpret_cast<__half2*>(&v.y));
            s.x += f0.x; s.y += f0.y; s.z += f1.x; s.w += f1.y;
        }
    }
}

// ---------------- reduce 1: seg1[w] = fp16(mean of fp16 x[src]) ----------------
__global__ void reduce1_kernel(const __half* __restrict__ xh, const int* __restrict__ offs,
                               const int* __restrict__ elist, __half* __restrict__ seg) {
    int w = (blockIdx.x * blockDim.x + threadIdx.x) >> 5;
    int lane = threadIdx.x & 31;
    if (w >= SCAN_N) return;
    int beg = __ldg(offs + w), end = __ldg(offs + w + 1);
    float4 s = make_float4(0.f, 0.f, 0.f, 0.f);
    gather_seg(xh, D_IN, elist, beg, end, lane, s);
    float sc = 1.f / fmaxf((float)(end - beg), 1.f);
    uint2 o;
    __half2 h0 = __floats2half2_rn(s.x * sc, s.y * sc);
    __half2 h1 = __floats2half2_rn(s.z * sc, s.w * sc);
    o.x = *reinterpret_cast<unsigned*>(&h0);
    o.y = *reinterpret_cast<unsigned*>(&h1);
    ((uint2*)(seg + (size_t)w * D_IN))[lane] = o;
}

// ---------------- fused reduce 2 + final (one warp per node, row-layout Yh) ----------------
__global__ void reduce2_final_kernel(const __half* __restrict__ Yh, const float* __restrict__ Ys,
                                     const int* __restrict__ offs, const int* __restrict__ elist,
                                     float* __restrict__ out) {
    int d = (blockIdx.x * blockDim.x + threadIdx.x) >> 5;
    int lane = threadIdx.x & 31;
    if (d >= NODES) return;

    int beg0 = __ldg(offs + d),             end0 = __ldg(offs + d + 1);
    int beg1 = __ldg(offs + NODES + d),     end1 = __ldg(offs + NODES + d + 1);
    int beg2 = __ldg(offs + 2 * NODES + d), end2 = __ldg(offs + 2 * NODES + d + 1);
    float4 acc = __ldg(((const float4*)(Ys + (size_t)d * D_OUT)) + lane);

    int begs[3] = {beg0, beg1, beg2};
    int ends[3] = {end0, end1, end2};
#pragma unroll
    for (int r = 0; r < RELS; r++) {
        int beg = begs[r], end = ends[r];
        if (beg == end) continue;
        float4 s = make_float4(0.f, 0.f, 0.f, 0.f);
        gather_seg(Yh + r * D_OUT, 3 * D_OUT, elist, beg, end, lane, s);
        float sc = 1.f / (float)(end - beg);
        acc.x += s.x * sc; acc.y += s.y * sc; acc.z += s.z * sc; acc.w += s.w * sc;
    }
    ((float4*)(out + (size_t)d * D_OUT))[lane] = acc;
}

// ---------------- fp16 HMMA GEMM: cp.async 3-stage, BK=64, ldmatrix fragments ----------------
// biasMode: 0=none, 1=bias[col] on all cols, 2=bias[col-halfCols] on fp32 cols only
#define BK 64
#define TSTRIDE 72
#define TILE_H (128 * TSTRIDE)
#define NSTAGE 3
#define GEMM_SMEM (NSTAGE * 2 * TILE_H * 2)   // 110592 bytes

__device__ __forceinline__ void ldsm_x4(uint32_t addr, unsigned& r0, unsigned& r1,
                                        unsigned& r2, unsigned& r3) {
    asm volatile("ldmatrix.sync.aligned.m8n8.x4.shared.b16 {%0,%1,%2,%3}, [%4];"
                 : "=r"(r0), "=r"(r1), "=r"(r2), "=r"(r3) : "r"(addr));
}

template <int D>
__global__ __launch_bounds__(256, 2)
void gemm_f16_kernel(const __half* __restrict__ feat, const __half* __restrict__ seg,
                     const __half* __restrict__ Bw, const float* __restrict__ bias,
                     float* __restrict__ Cf, __half* __restrict__ Ch,
                     int M, int N, int K, int halfCols, int doRelu, int biasMode) {
    extern __shared__ __half smp[];
    __half* As = smp;
    __half* Bs = smp + NSTAGE * TILE_H;
    const uint32_t As_u = (uint32_t)__cvta_generic_to_shared(As);
    const uint32_t Bs_u = (uint32_t)__cvta_generic_to_shared(Bs);

    const int tid  = threadIdx.x;
    const int lane = tid & 31;
    const int warp = tid >> 5;
    const int warpM = (warp >> 2) * 64;
    const int warpN = (warp & 3) * 32;
    const int block_row = blockIdx.x * 128;
    const int block_col = blockIdx.y * 128;

    const int ld_r0 = tid >> 1;
    const int ld_c0 = (tid & 1) * 32;

    const int a_row_lane = ((lane >> 3) & 1) * 8 + (lane & 7);
    const int a_k_lane   = (lane >> 4) * 8;
    const int b_n_lane = (lane >> 4) * 8 + (lane & 7);
    const int b_k_lane = ((lane >> 3) & 1) * 8;

    float acc[4][4][4];
#pragma unroll
    for (int i = 0; i < 4; i++)
#pragma unroll
        for (int j = 0; j < 4; j++)
#pragma unroll
            for (int c = 0; c < 4; c++) acc[i][j][c] = 0.f;

    auto load_stage = [&](int buf, int kb) {
        const int chunk = kb / D;
        const int col0 = kb - chunk * D;
        const __half* abase = (chunk == 0) ? feat : (seg + (size_t)(chunk - 1) * NODES * D);
        int gr = block_row + ld_r0;
        const __half* ag = abase + (size_t)gr * D + col0 + ld_c0;
        uint32_t sa = As_u + (uint32_t)(buf * TILE_H + ld_r0 * TSTRIDE + ld_c0) * 2u;
        int sz = (gr < M) ? 16 : 0;
#pragma unroll
        for (int l = 0; l < 4; l++) {
            asm volatile("cp.async.cg.shared.global [%0], [%1], 16, %2;"
                         :: "r"(sa + l * 16u), "l"(ag + l * 8), "r"(sz));
        }
        const __half* bg = Bw + (size_t)(block_col + ld_r0) * K + kb + ld_c0;
        uint32_t sb = Bs_u + (uint32_t)(buf * TILE_H + ld_r0 * TSTRIDE + ld_c0) * 2u;
#pragma unroll
        for (int l = 0; l < 4; l++) {
            asm volatile("cp.async.cg.shared.global [%0], [%1], 16;"
                         :: "r"(sb + l * 16u), "l"(bg + l * 8));
        }
        asm volatile("cp.async.commit_group;");
    };

    const int T = K / BK;
    load_stage(0, 0);
    load_stage(1, BK);

    for (int t = 0; t < T; t++) {
        if (t + 1 < T) {
            asm volatile("cp.async.wait_group 1;");
        } else {
            asm volatile("cp.async.wait_group 0;");
        }
        __syncthreads();
        if (t + 2 < T) load_stage((t + 2) % NSTAGE, (t + 2) * BK);

        int buf = t % NSTAGE;
        const uint32_t At_u = As_u + (uint32_t)(buf * TILE_H) * 2u;
        const uint32_t Bt_u = Bs_u + (uint32_t)(buf * TILE_H) * 2u;
#pragma unroll
        for (int k16 = 0; k16 < BK / 16; k16++) {
            const int kbase = k16 * 16;
            unsigned a[4][4];
#pragma unroll
            for (int mt = 0; mt < 4; mt++) {
                uint32_t addr = At_u + (uint32_t)((warpM + mt * 16 + a_row_lane) * TSTRIDE
                                                  + kbase + a_k_lane) * 2u;
                ldsm_x4(addr, a[mt][0], a[mt][1], a[mt][2], a[mt][3]);
            }
            unsigned b[4][2];
#pragma unroll
            for (int ntp = 0; ntp < 4; ntp += 2) {
                uint32_t addr = Bt_u + (uint32_t)((warpN + ntp * 8 + b_n_lane) * TSTRIDE
                                                  + kbase + b_k_lane) * 2u;
                ldsm_x4(addr, b[ntp][0], b[ntp][1], b[ntp + 1][0], b[ntp + 1][1]);
            }
#pragma unroll
            for (int mt = 0; mt < 4; mt++)
#pragma unroll
                for (int nt = 0; nt < 4; nt++) {
                    asm volatile(
                        "mma.sync.aligned.m16n8k16.row.col.f32.f16.f16.f32 "
                        "{%0,%1,%2,%3}, {%4,%5,%6,%7}, {%8,%9}, {%0,%1,%2,%3};"
                        : "+f"(acc[mt][nt][0]), "+f"(acc[mt][nt][1]),
                          "+f"(acc[mt][nt][2]), "+f"(acc[mt][nt][3])
                        : "r"(a[mt][0]), "r"(a[mt][1]), "r"(a[mt][2]), "r"(a[mt][3]),
                          "r"(b[nt][0]), "r"(b[nt][1]));
                }
        }
        __syncthreads();
    }

    const int fStride = N - halfCols;
#pragma unroll
    for (int mt = 0; mt < 4; mt++) {
#pragma unroll
        for (int nt = 0; nt < 4; nt++) {
            int col = block_col + warpN + nt * 8 + (lane & 3) * 2;
            float bx = 0.f, by = 0.f;
            if (biasMode == 1) { bx = bias[col]; by = bias[col + 1]; }
            else if (biasMode == 2 && col >= halfCols) {
                bx = bias[col - halfCols]; by = bias[col - halfCols + 1];
            }
#pragma unroll
            for (int half = 0; half < 2; half++) {
                int row = block_row + warpM + mt * 16 + (lane >> 2) + half * 8;
                if (row >= M) continue;
                float vx = acc[mt][nt][half * 2 + 0] + bx;
                float vy = acc[mt][nt][half * 2 + 1] + by;
                if (doRelu) { vx = fmaxf(vx, 0.f); vy = fmaxf(vy, 0.f); }
                if (col < halfCols) {
                    *(__half2*)(Ch + (size_t)row * halfCols + col) = __floats2half2_rn(vx, vy);
                } else {
                    *(float2*)(Cf + (size_t)row * fStride + (col - halfCols)) = make_float2(vx, vy);
                }
            }
        }
    }
}

// ---------------- launch ----------------
extern "C" void kernel_launch(void* const* d_in, const int* in_sizes, int n_in,
                              void* d_out, int out_size) {
    const float* x      = (const float*)d_in[0];
    const int*   src    = (const int*)  d_in[1];
    const int*   dst    = (const int*)  d_in[2];
    const float* Wself1 = (const float*)d_in[3];
    const float* Wneigh1= (const float*)d_in[4];
    const float* b1     = (const float*)d_in[5];
    const float* Wself2 = (const float*)d_in[6];
    const float* Wneigh2= (const float*)d_in[7];
    const float* b2     = (const float*)d_in[8];
    float* out = (float*)d_out;

    float *Ys, *b1s, *b2s;
    __half *xh, *seg1, *h, *Yh, *W1h, *W2h;
    int *cnt, *offs, *bsum, *epos, *elist;
    cudaGetSymbolAddress((void**)&xh,   g_xh);
    cudaGetSymbolAddress((void**)&seg1, g_seg1);
    cudaGetSymbolAddress((void**)&h,    g_h);
    cudaGetSymbolAddress((void**)&Yh,   g_Yh);
    cudaGetSymbolAddress((void**)&Ys,   g_Ys);
    cudaGetSymbolAddress((void**)&cnt,  g_cnt);
    cudaGetSymbolAddress((void**)&offs, g_offs);
    cudaGetSymbolAddress((void**)&bsum, g_bsum);
    cudaGetSymbolAddress((void**)&epos, g_epos);
    cudaGetSymbolAddress((void**)&elist,g_elist);
    cudaGetSymbolAddress((void**)&W1h,  g_W1h);
    cudaGetSymbolAddress((void**)&W2h,  g_W2h);
    cudaGetSymbolAddress((void**)&b1s,  g_b1s);
    cudaGetSymbolAddress((void**)&b2s,  g_b2s);

    cudaFuncSetAttribute(gemm_f16_kernel<D_IN>,
                         cudaFuncAttributeMaxDynamicSharedMemorySize, GEMM_SMEM);
    cudaFuncSetAttribute(gemm_f16_kernel<D_HID>,
                         cudaFuncAttributeMaxDynamicSharedMemorySize, GEMM_SMEM);

    // ---- zero cnt, then fused cnt(+rank capture) + all prep ----
    zero_cnt_kernel<<<(SCAN_N / 4 + 255) / 256, 256>>>((int4*)cnt);
    cnt_prep_kernel<<<(RELS * EDGES + 255) / 256, 256>>>(
        dst, cnt, epos, (const float4*)x,
        Wself1, Wneigh1, b1, Wself2, Wneigh2, b2,
        W1h, W2h, (uint4*)xh, b1s, b2s);

    // ---- CSR scans + atomic-free fill ----
    scan1_kernel<<<SCAN_BLOCKS, SCAN_B>>>(cnt, offs, bsum);
    scan2_kernel<<<1, SCAN_B>>>(bsum, SCAN_BLOCKS);
    scan3_kernel<<<SCAN_BLOCKS, SCAN_B>>>(offs, bsum);
    fill_kernel<<<(RELS * EDGES + 255) / 256, 256>>>(src, dst, offs, epos, elist);

    const int reduce_blocks = (SCAN_N * 32 + 255) / 256;
    const int mblocks = (NODES + 127) / 128;

    // ---- layer 1: fp16 means -> seg1, fp16 GEMM -> h (relu+bias, fp16 out) ----
    reduce1_kernel<<<reduce_blocks, 256>>>(xh, offs, elist, seg1);
    {
        dim3 grid(mblocks, D_HID / 128);
        gemm_f16_kernel<D_IN><<<grid, 256, GEMM_SMEM>>>(xh, seg1, W1h, b1s, nullptr, h,
                                                        NODES, D_HID, 4 * D_IN,
                                                        D_HID, 1, 1);
    }

    // ---- layer 2: fp16 GEMM -> [Yh fp16 | Ys fp32+bias], fused reduce+final -> out ----
    {
        dim3 grid(mblocks, (4 * D_OUT) / 128);
        gemm_f16_kernel<D_HID><<<grid, 256, GEMM_SMEM>>>(h, nullptr, W2h, b2s, Ys, Yh,
                                                         NODES, 4 * D_OUT, D_HID,
                                                         3 * D_OUT, 0, 2);
    }
    reduce2_final_kernel<<<(NODES * 32 + 255) / 256, 256>>>(Yh, Ys, offs, elist, out);
}

// round 17
// speedup vs baseline: 1.0218x; 1.0004x over previous
#include <cuda_runtime.h>
#include <cuda_fp16.h>
#include <cstdint>

// ---------------- problem constants ----------------
#define NODES 50000
#define RELS  3
#define EDGES 600000
#define D_IN  128
#define D_HID 256
#define D_OUT 128

#define SCAN_N (RELS * NODES)          // 150000 segments
#define SCAN_B 512
#define SCAN_BLOCKS ((SCAN_N + SCAN_B - 1) / SCAN_B)   // 293

// ---------------- scratch ----------------
__device__ __half g_xh  [(size_t)NODES * D_IN];           // 12.8 MB
__device__ __half g_seg1[(size_t)RELS * NODES * D_IN];    // 38.4 MB
__device__ __half g_h   [(size_t)NODES * D_HID];          // 25.6 MB
__device__ __half g_Yh  [(size_t)NODES * 3 * D_OUT];      // 38.4 MB, row layout [node][3*128]
__device__ float  g_Ys  [(size_t)NODES * D_OUT];          // 25.6 MB (bias pre-added)
__device__ int    g_cnt [SCAN_N];
__device__ int    g_offs[SCAN_N + 1];                     // within-block partial prefixes
__device__ int    g_offsF[SCAN_N + 1];                    // finalized offsets (written in fill)
__device__ int    g_bsum[SCAN_B];                         // block sums -> exclusive scan in place
__device__ int    g_scan_done;
__device__ int    g_epos[(size_t)RELS * EDGES];           // 7.2 MB per-edge rank in segment
__device__ int    g_elist[(size_t)RELS * EDGES];          // 7.2 MB
__device__ __half g_W1h [D_HID * (4 * D_IN)];             // [256][512] fp16, transposed
__device__ __half g_W2h [(4 * D_OUT) * D_HID];            // [512][256] fp16, transposed
__device__ float  g_b1s [D_HID];
__device__ float  g_b2s [D_OUT];

// ---------------- tiny zero for cnt + scan_done ----------------
__global__ void zero_cnt_kernel(int4* __restrict__ p, int* __restrict__ scan_done) {
    int i = blockIdx.x * blockDim.x + threadIdx.x;
    if (i < SCAN_N / 4) p[i] = make_int4(0, 0, 0, 0);
    if (i == 0) *scan_done = 0;
}

// ---------------- fused cnt + prep: count degrees (capturing per-edge rank) + convert ----
__global__ void cnt_prep_kernel(const int* __restrict__ dst, int* __restrict__ cnt,
                                int* __restrict__ epos,
                                const float4* __restrict__ x,
                                const float* __restrict__ Wself1, const float* __restrict__ Wneigh1,
                                const float* __restrict__ b1,
                                const float* __restrict__ Wself2, const float* __restrict__ Wneigh2,
                                const float* __restrict__ b2,
                                __half* __restrict__ W1t, __half* __restrict__ W2t,
                                uint4* __restrict__ xh,
                                float* __restrict__ b1s, float* __restrict__ b2s) {
    const int t = blockIdx.x * blockDim.x + threadIdx.x;

    if (t < RELS * EDGES) {
        int r = t / EDGES;
        epos[t] = atomicAdd(&cnt[r * NODES + dst[t]], 1);
    }

    if (t < NODES * D_IN / 8) {
        float4 a = x[(long)t * 2], b = x[(long)t * 2 + 1];
        __half2 h0 = __floats2half2_rn(a.x, a.y);
        __half2 h1 = __floats2half2_rn(a.z, a.w);
        __half2 h2 = __floats2half2_rn(b.x, b.y);
        __half2 h3 = __floats2half2_rn(b.z, b.w);
        uint4 o;
        o.x = *reinterpret_cast<unsigned*>(&h0);
        o.y = *reinterpret_cast<unsigned*>(&h1);
        o.z = *reinterpret_cast<unsigned*>(&h2);
        o.w = *reinterpret_cast<unsigned*>(&h3);
        xh[t] = o;
    }

    if (t < D_HID * 4 * D_IN) {
        int j = t / (4 * D_IN);
        int k = t - j * (4 * D_IN);
        float v;
        if (k < D_IN) {
            v = Wself1[(size_t)k * D_HID + j]
              + Wself1[((size_t)D_IN + k) * D_HID + j]
              + Wself1[((size_t)2 * D_IN + k) * D_HID + j];
        } else {
            int r = (k - D_IN) / D_IN;
            int d = (k - D_IN) - r * D_IN;
            v = Wneigh1[((size_t)r * D_IN + d) * D_HID + j];
        }
        W1t[t] = __float2half_rn(v);
    }

    if (t < (4 * D_OUT) * D_HID) {
        int c = t / D_HID;
        int k = t - c * D_HID;
        float v;
        if (c < 3 * D_OUT) {
            int r = c / D_OUT;
            int j = c - r * D_OUT;
            v = Wneigh2[((size_t)r * D_HID + k) * D_OUT + j];
        } else {
            int j = c - 3 * D_OUT;
            v = Wself2[(size_t)k * D_OUT + j]
              + Wself2[((size_t)D_HID + k) * D_OUT + j]
              + Wself2[((size_t)2 * D_HID + k) * D_OUT + j];
        }
        W2t[t] = __float2half_rn(v);
    }

    if (t < D_HID) b1s[t] = b1[t] + b1[D_HID + t] + b1[2 * D_HID + t];
    if (t < D_OUT) b2s[t] = b2[t] + b2[D_OUT + t] + b2[2 * D_OUT + t];
}

// ---------------- fused scan: block prefixes + last-block exclusive scan of bsum ----------
__global__ void scan_fused_kernel(const int* __restrict__ cnt, int* __restrict__ offs,
                                  int* __restrict__ bsum, int* __restrict__ scan_done) {
    __shared__ int wsum[16];
    int i = blockIdx.x * SCAN_B + threadIdx.x;
    int lane = threadIdx.x & 31, wid = threadIdx.x >> 5;
    int v = (i < SCAN_N) ? cnt[i] : 0;
    int s = v;
#pragma unroll
    for (int o = 1; o < 32; o <<= 1) {
        int t = __shfl_up_sync(0xffffffffu, s, o);
        if (lane >= o) s += t;
    }
    if (lane == 31) wsum[wid] = s;
    __syncthreads();
    if (wid == 0) {
        int ws = (lane < 16) ? wsum[lane] : 0;
#pragma unroll
        for (int o = 1; o < 16; o <<= 1) {
            int t = __shfl_up_sync(0xffffffffu, ws, o);
            if (lane >= o) ws += t;
        }
        if (lane < 16) wsum[lane] = ws;
    }
    __syncthreads();
    int incl = s + ((wid > 0) ? wsum[wid - 1] : 0);
    if (i < SCAN_N) offs[i] = incl - v;
    if (threadIdx.x == SCAN_B - 1) bsum[blockIdx.x] = incl;

    // last block to arrive exclusive-scans bsum in place
    __shared__ int is_last;
    __threadfence();
    __syncthreads();
    if (threadIdx.x == 0) {
        int prev = atomicAdd(scan_done, 1);
        is_last = (prev == (int)gridDim.x - 1);
    }
    __syncthreads();
    if (!is_last) return;

    int bv = (threadIdx.x < SCAN_BLOCKS) ? bsum[threadIdx.x] : 0;
    int bs = bv;
#pragma unroll
    for (int o = 1; o < 32; o <<= 1) {
        int t = __shfl_up_sync(0xffffffffu, bs, o);
        if (lane >= o) bs += t;
    }
    if (lane == 31) wsum[wid] = bs;
    __syncthreads();
    if (wid == 0) {
        int ws = (lane < 16) ? wsum[lane] : 0;
#pragma unroll
        for (int o = 1; o < 16; o <<= 1) {
            int t = __shfl_up_sync(0xffffffffu, ws, o);
            if (lane >= o) ws += t;
        }
        if (lane < 16) wsum[lane] = ws;
    }
    __syncthreads();
    int bincl = bs + ((wid > 0) ? wsum[wid - 1] : 0);
    if (threadIdx.x < SCAN_BLOCKS) bsum[threadIdx.x] = bincl - bv;
}

// ---------------- fill: atomic-free scatter + offset finalization into offsF ----------------
__global__ void fill_kernel(const int* __restrict__ src, const int* __restrict__ dst,
                            const int* __restrict__ offs, const int* __restrict__ bscan,
                            const int* __restrict__ epos, int* __restrict__ elist,
                            int* __restrict__ offsF) {
    int e = blockIdx.x * blockDim.x + threadIdx.x;

    // finalize offsets for downstream consumers (separate array; no race with reads below)
    if (e < SCAN_N) offsF[e] = __ldg(offs + e) + __ldg(bscan + (e >> 9));
    if (e == SCAN_N) offsF[SCAN_N] = RELS * EDGES;

    if (e >= RELS * EDGES) return;
    int r = e / EDGES;
    int idx = r * NODES + dst[e];
    int base = __ldg(offs + idx) + __ldg(bscan + (idx >> 9));
    elist[base + epos[e]] = src[e];
}

// ---------------- gather-accumulate helper: batches of 8 / 4 / 1 ----------------
__device__ __forceinline__ void gather_seg(const __half* __restrict__ base, size_t rowStride,
                                           const int* __restrict__ elist, int beg, int end,
                                           int lane, float4& s) {
    for (int i = beg; i < end; i += 32) {
        int nid = (i + lane < end) ? elist[i + lane] : 0;
        int cnt = min(32, end - i);
        int j = 0;
        for (; j + 8 <= cnt; j += 8) {
            int sid[8];
#pragma unroll
            for (int q = 0; q < 8; q++) sid[q] = __shfl_sync(0xffffffffu, nid, j + q);
            uint2 v[8];
#pragma unroll
            for (int q = 0; q < 8; q++)
                v[q] = __ldg(((const uint2*)(base + (size_t)sid[q] * rowStride)) + lane);
#pragma unroll
            for (int q = 0; q < 8; q++) {
                float2 f0 = __half22float2(*reinterpret_cast<__half2*>(&v[q].x));
                float2 f1 = __half22float2(*reinterpret_cast<__half2*>(&v[q].y));
                s.x += f0.x; s.y += f0.y; s.z += f1.x; s.w += f1.y;
            }
        }
        for (; j + 4 <= cnt; j += 4) {
            int sid[4];
#pragma unroll
            for (int q = 0; q < 4; q++) sid[q] = __shfl_sync(0xffffffffu, nid, j + q);
            uint2 v[4];
#pragma unroll
            for (int q = 0; q < 4; q++)
                v[q] = __ldg(((const uint2*)(base + (size_t)sid[q] * rowStride)) + lane);
#pragma unroll
            for (int q = 0; q < 4; q++) {
                float2 f0 = __half22float2(*reinterpret_cast<__half2*>(&v[q].x));
                float2 f1 = __half22float2(*reinterpret_cast<__half2*>(&v[q].y));
                s.x += f0.x; s.y += f0.y; s.z += f1.x; s.w += f1.y;
            }
        }
        for (; j < cnt; j++) {
            int sid = __shfl_sync(0xffffffffu, nid, j);
            uint2 v = __ldg(((const uint2*)(base + (size_t)sid * rowStride)) + lane);
            float2 f0 = __half22float2(*reinterpret_cast<__half2*>(&v.x));
            float2 f1 = __half22float2(*reinterpret_cast<__half2*>(&v.y));
            s.x += f0.x; s.y += f0.y; s.z += f1.x; s.w += f1.y;
        }
    }
}

// ---------------- reduce 1: seg1[w] = fp16(mean of fp16 x[src]) ----------------
__global__ void reduce1_kernel(const __half* __restrict__ xh, const int* __restrict__ offs,
                               const int* __restrict__ elist, __half* __restrict__ seg) {
    int w = (blockIdx.x * blockDim.x + threadIdx.x) >> 5;
    int lane = threadIdx.x & 31;
    if (w >= SCAN_N) return;
    int beg = __ldg(offs + w), end = __ldg(offs + w + 1);
    float4 s = make_float4(0.f, 0.f, 0.f, 0.f);
    gather_seg(xh, D_IN, elist, beg, end, lane, s);
    float sc = 1.f / fmaxf((float)(end - beg), 1.f);
    uint2 o;
    __half2 h0 = __floats2half2_rn(s.x * sc, s.y * sc);
    __half2 h1 = __floats2half2_rn(s.z * sc, s.w * sc);
    o.x = *reinterpret_cast<unsigned*>(&h0);
    o.y = *reinterpret_cast<unsigned*>(&h1);
    ((uint2*)(seg + (size_t)w * D_IN))[lane] = o;
}

// ---------------- fused reduce 2 + final (one warp per node, row-layout Yh) ----------------
__global__ void reduce2_final_kernel(const __half* __restrict__ Yh, const float* __restrict__ Ys,
                                     const int* __restrict__ offs, const int* __restrict__ elist,
                                     float* __restrict__ out) {
    int d = (blockIdx.x * blockDim.x + threadIdx.x) >> 5;
    int lane = threadIdx.x & 31;
    if (d >= NODES) return;

    int beg0 = __ldg(offs + d),             end0 = __ldg(offs + d + 1);
    int beg1 = __ldg(offs + NODES + d),     end1 = __ldg(offs + NODES + d + 1);
    int beg2 = __ldg(offs + 2 * NODES + d), end2 = __ldg(offs + 2 * NODES + d + 1);
    float4 acc = __ldg(((const float4*)(Ys + (size_t)d * D_OUT)) + lane);

    int begs[3] = {beg0, beg1, beg2};
    int ends[3] = {end0, end1, end2};
#pragma unroll
    for (int r = 0; r < RELS; r++) {
        int beg = begs[r], end = ends[r];
        if (beg == end) continue;
        float4 s = make_float4(0.f, 0.f, 0.f, 0.f);
        gather_seg(Yh + r * D_OUT, 3 * D_OUT, elist, beg, end, lane, s);
        float sc = 1.f / (float)(end - beg);
        acc.x += s.x * sc; acc.y += s.y * sc; acc.z += s.z * sc; acc.w += s.w * sc;
    }
    ((float4*)(out + (size_t)d * D_OUT))[lane] = acc;
}

// ---------------- fp16 HMMA GEMM: cp.async 3-stage, BK=64, ldmatrix fragments ----------------
// biasMode: 0=none, 1=bias[col] on all cols, 2=bias[col-halfCols] on fp32 cols only
#define BK 64
#define TSTRIDE 72
#define TILE_H (128 * TSTRIDE)
#define NSTAGE 3
#define GEMM_SMEM (NSTAGE * 2 * TILE_H * 2)   // 110592 bytes

__device__ __forceinline__ void ldsm_x4(uint32_t addr, unsigned& r0, unsigned& r1,
                                        unsigned& r2, unsigned& r3) {
    asm volatile("ldmatrix.sync.aligned.m8n8.x4.shared.b16 {%0,%1,%2,%3}, [%4];"
                 : "=r"(r0), "=r"(r1), "=r"(r2), "=r"(r3) : "r"(addr));
}

template <int D>
__global__ __launch_bounds__(256, 2)
void gemm_f16_kernel(const __half* __restrict__ feat, const __half* __restrict__ seg,
                     const __half* __restrict__ Bw, const float* __restrict__ bias,
                     float* __restrict__ Cf, __half* __restrict__ Ch,
                     int M, int N, int K, int halfCols, int doRelu, int biasMode) {
    extern __shared__ __half smp[];
    __half* As = smp;
    __half* Bs = smp + NSTAGE * TILE_H;
    const uint32_t As_u = (uint32_t)__cvta_generic_to_shared(As);
    const uint32_t Bs_u = (uint32_t)__cvta_generic_to_shared(Bs);

    const int tid  = threadIdx.x;
    const int lane = tid & 31;
    const int warp = tid >> 5;
    const int warpM = (warp >> 2) * 64;
    const int warpN = (warp & 3) * 32;
    const int block_row = blockIdx.x * 128;
    const int block_col = blockIdx.y * 128;

    const int ld_r0 = tid >> 1;
    const int ld_c0 = (tid & 1) * 32;

    const int a_row_lane = ((lane >> 3) & 1) * 8 + (lane & 7);
    const int a_k_lane   = (lane >> 4) * 8;
    const int b_n_lane = (lane >> 4) * 8 + (lane & 7);
    const int b_k_lane = ((lane >> 3) & 1) * 8;

    float acc[4][4][4];
#pragma unroll
    for (int i = 0; i < 4; i++)
#pragma unroll
        for (int j = 0; j < 4; j++)
#pragma unroll
            for (int c = 0; c < 4; c++) acc[i][j][c] = 0.f;

    auto load_stage = [&](int buf, int kb) {
        const int chunk = kb / D;
        const int col0 = kb - chunk * D;
        const __half* abase = (chunk == 0) ? feat : (seg + (size_t)(chunk - 1) * NODES * D);
        int gr = block_row + ld_r0;
        const __half* ag = abase + (size_t)gr * D + col0 + ld_c0;
        uint32_t sa = As_u + (uint32_t)(buf * TILE_H + ld_r0 * TSTRIDE + ld_c0) * 2u;
        int sz = (gr < M) ? 16 : 0;
#pragma unroll
        for (int l = 0; l < 4; l++) {
            asm volatile("cp.async.cg.shared.global [%0], [%1], 16, %2;"
                         :: "r"(sa + l * 16u), "l"(ag + l * 8), "r"(sz));
        }
        const __half* bg = Bw + (size_t)(block_col + ld_r0) * K + kb + ld_c0;
        uint32_t sb = Bs_u + (uint32_t)(buf * TILE_H + ld_r0 * TSTRIDE + ld_c0) * 2u;
#pragma unroll
        for (int l = 0; l < 4; l++) {
            asm volatile("cp.async.cg.shared.global [%0], [%1], 16;"
                         :: "r"(sb + l * 16u), "l"(bg + l * 8));
        }
        asm volatile("cp.async.commit_group;");
    };

    const int T = K / BK;
    load_stage(0, 0);
    load_stage(1, BK);

    for (int t = 0; t < T; t++) {
        if (t + 1 < T) {
            asm volatile("cp.async.wait_group 1;");
        } else {
            asm volatile("cp.async.wait_group 0;");
        }
        __syncthreads();
        if (t + 2 < T) load_stage((t + 2) % NSTAGE, (t + 2) * BK);

        int buf = t % NSTAGE;
        const uint32_t At_u = As_u + (uint32_t)(buf * TILE_H) * 2u;
        const uint32_t Bt_u = Bs_u + (uint32_t)(buf * TILE_H) * 2u;
#pragma unroll
        for (int k16 = 0; k16 < BK / 16; k16++) {
            const int kbase = k16 * 16;
            unsigned a[4][4];
#pragma unroll
            for (int mt = 0; mt < 4; mt++) {
                uint32_t addr = At_u + (uint32_t)((warpM + mt * 16 + a_row_lane) * TSTRIDE
                                                  + kbase + a_k_lane) * 2u;
                ldsm_x4(addr, a[mt][0], a[mt][1], a[mt][2], a[mt][3]);
            }
            unsigned b[4][2];
#pragma unroll
            for (int ntp = 0; ntp < 4; ntp += 2) {
                uint32_t addr = Bt_u + (uint32_t)((warpN + ntp * 8 + b_n_lane) * TSTRIDE
                                                  + kbase + b_k_lane) * 2u;
                ldsm_x4(addr, b[ntp][0], b[ntp][1], b[ntp + 1][0], b[ntp + 1][1]);
            }
#pragma unroll
            for (int mt = 0; mt < 4; mt++)
#pragma unroll
                for (int nt = 0; nt < 4; nt++) {
                    asm volatile(
                        "mma.sync.aligned.m16n8k16.row.col.f32.f16.f16.f32 "
                        "{%0,%1,%2,%3}, {%4,%5,%6,%7}, {%8,%9}, {%0,%1,%2,%3};"
                        : "+f"(acc[mt][nt][0]), "+f"(acc[mt][nt][1]),
                          "+f"(acc[mt][nt][2]), "+f"(acc[mt][nt][3])
                        : "r"(a[mt][0]), "r"(a[mt][1]), "r"(a[mt][2]), "r"(a[mt][3]),
                          "r"(b[nt][0]), "r"(b[nt][1]));
                }
        }
        __syncthreads();
    }

    const int fStride = N - halfCols;
#pragma unroll
    for (int mt = 0; mt < 4; mt++) {
#pragma unroll
        for (int nt = 0; nt < 4; nt++) {
            int col = block_col + warpN + nt * 8 + (lane & 3) * 2;
            float bx = 0.f, by = 0.f;
            if (biasMode == 1) { bx = bias[col]; by = bias[col + 1]; }
            else if (biasMode == 2 && col >= halfCols) {
                bx = bias[col - halfCols]; by = bias[col - halfCols + 1];
            }
#pragma unroll
            for (int half = 0; half < 2; half++) {
                int row = block_row + warpM + mt * 16 + (lane >> 2) + half * 8;
                if (row >= M) continue;
                float vx = acc[mt][nt][half * 2 + 0] + bx;
                float vy = acc[mt][nt][half * 2 + 1] + by;
                if (doRelu) { vx = fmaxf(vx, 0.f); vy = fmaxf(vy, 0.f); }
                if (col < halfCols) {
                    *(__half2*)(Ch + (size_t)row * halfCols + col) = __floats2half2_rn(vx, vy);
                } else {
                    *(float2*)(Cf + (size_t)row * fStride + (col - halfCols)) = make_float2(vx, vy);
                }
            }
        }
    }
}

// ---------------- launch ----------------
extern "C" void kernel_launch(void* const* d_in, const int* in_sizes, int n_in,
                              void* d_out, int out_size) {
    const float* x      = (const float*)d_in[0];
    const int*   src    = (const int*)  d_in[1];
    const int*   dst    = (const int*)  d_in[2];
    const float* Wself1 = (const float*)d_in[3];
    const float* Wneigh1= (const float*)d_in[4];
    const float* b1     = (const float*)d_in[5];
    const float* Wself2 = (const float*)d_in[6];
    const float* Wneigh2= (const float*)d_in[7];
    const float* b2     = (const float*)d_in[8];
    float* out = (float*)d_out;

    float *Ys, *b1s, *b2s;
    __half *xh, *seg1, *h, *Yh, *W1h, *W2h;
    int *cnt, *offs, *offsF, *bsum, *epos, *elist, *scan_done;
    cudaGetSymbolAddress((void**)&xh,   g_xh);
    cudaGetSymbolAddress((void**)&seg1, g_seg1);
    cudaGetSymbolAddress((void**)&h,    g_h);
    cudaGetSymbolAddress((void**)&Yh,   g_Yh);
    cudaGetSymbolAddress((void**)&Ys,   g_Ys);
    cudaGetSymbolAddress((void**)&cnt,  g_cnt);
    cudaGetSymbolAddress((void**)&offs, g_offs);
    cudaGetSymbolAddress((void**)&offsF,g_offsF);
    cudaGetSymbolAddress((void**)&bsum, g_bsum);
    cudaGetSymbolAddress((void**)&epos, g_epos);
    cudaGetSymbolAddress((void**)&elist,g_elist);
    cudaGetSymbolAddress((void**)&scan_done, g_scan_done);
    cudaGetSymbolAddress((void**)&W1h,  g_W1h);
    cudaGetSymbolAddress((void**)&W2h,  g_W2h);
    cudaGetSymbolAddress((void**)&b1s,  g_b1s);
    cudaGetSymbolAddress((void**)&b2s,  g_b2s);

    cudaFuncSetAttribute(gemm_f16_kernel<D_IN>,
                         cudaFuncAttributeMaxDynamicSharedMemorySize, GEMM_SMEM);
    cudaFuncSetAttribute(gemm_f16_kernel<D_HID>,
                         cudaFuncAttributeMaxDynamicSharedMemorySize, GEMM_SMEM);

    // ---- zero cnt + scan_done, then fused cnt(+rank capture) + all prep ----
    zero_cnt_kernel<<<(SCAN_N / 4 + 255) / 256, 256>>>((int4*)cnt, scan_done);
    cnt_prep_kernel<<<(RELS * EDGES + 255) / 256, 256>>>(
        dst, cnt, epos, (const float4*)x,
        Wself1, Wneigh1, b1, Wself2, Wneigh2, b2,
        W1h, W2h, (uint4*)xh, b1s, b2s);

    // ---- fused scan (block prefixes + last-block bsum scan), then fill(+offset finalize) ----
    scan_fused_kernel<<<SCAN_BLOCKS, SCAN_B>>>(cnt, offs, bsum, scan_done);
    fill_kernel<<<(RELS * EDGES + 255) / 256, 256>>>(src, dst, offs, bsum, epos, elist, offsF);

    const int reduce_blocks = (SCAN_N * 32 + 255) / 256;
    const int mblocks = (NODES + 127) / 128;

    // ---- layer 1: fp16 means -> seg1, fp16 GEMM -> h (relu+bias, fp16 out) ----
    reduce1_kernel<<<reduce_blocks, 256>>>(xh, offsF, elist, seg1);
    {
        dim3 grid(mblocks, D_HID / 128);
        gemm_f16_kernel<D_IN><<<grid, 256, GEMM_SMEM>>>(xh, seg1, W1h, b1s, nullptr, h,
                                                        NODES, D_HID, 4 * D_IN,
                                                        D_HID, 1, 1);
    }

    // ---- layer 2: fp16 GEMM -> [Yh fp16 | Ys fp32+bias], fused reduce+final -> out ----
    {
        dim3 grid(mblocks, (4 * D_OUT) / 128);
        gemm_f16_kernel<D_HID><<<grid, 256, GEMM_SMEM>>>(h, nullptr, W2h, b2s, Ys, Yh,
                                                         NODES, 4 * D_OUT, D_HID,
                                                         3 * D_OUT, 0, 2);
    }
    reduce2_final_kernel<<<(NODES * 32 + 255) / 256, 256>>>(Yh, Ys, offsF, elist, out);
}